// round 12
// baseline (speedup 1.0000x reference)
#include <cuda_runtime.h>
#include <math.h>
#include <stdint.h>

// Shapes (fixed by the problem)
#define BB   4
#define NN   2048
#define DD   1024
#define DLL  64
#define DKK  128
#define DCC  8

// -------- device scratch (static: no allocations allowed) --------
__device__ float g_lam[BB];
__device__ float g_q[BB*DKK];        // q / tau
__device__ float g_qB[BB*DCC*DKK];   // (q/tau)^T basis_r
__device__ float g_u[BB*9*DD];       // u_0 = W_K^T (q/tau); u_r = W_K^T qB_r
__device__ float g_score[BB*NN];
__device__ float g_screen[BB*NN];
__device__ float g_yp[16*BB*DD];     // partial y over 16 n-chunks

// ======== K1: q[b,a] (scaled by 1/tau) — grid (128 a, 4 b), 128 thr ========
__global__ void __launch_bounds__(128) k_q(
    const float* __restrict__ xq, const float* __restrict__ zq,
    const float* __restrict__ WQ, const float* __restrict__ WQz,
    const float* __restrict__ WQg) {
    int a = blockIdx.x, b = blockIdx.y;
    int t = threadIdx.x;
    __shared__ float zs[DLL];
    __shared__ float red[128];
    if (t < DLL) zs[t] = zq[b*DLL + t];
    __syncthreads();
    float s = 0.f;
    const float4* wq = (const float4*)(WQ + (size_t)a*DD);
    const float4* x  = (const float4*)(xq + (size_t)b*DD);
    #pragma unroll 2
    for (int d = t; d < DD/4; d += 128) {
        float4 wv = wq[d], xv = x[d];
        s += xv.x*wv.x + xv.y*wv.y + xv.z*wv.z + xv.w*wv.w;
    }
    if (t < DLL) s += zs[t]*WQz[a*DLL + t];
    const float* G = WQg + (size_t)a*DLL*DLL;
    #pragma unroll 4
    for (int idx = t; idx < DLL*DLL; idx += 128)
        s += G[idx]*zs[idx >> 6]*zs[idx & 63];
    red[t] = s; __syncthreads();
    for (int off = 64; off > 0; off >>= 1) {
        if (t < off) red[t] += red[t+off];
        __syncthreads();
    }
    if (t == 0) {
        float rsq = 0.f;
        for (int l = 0; l < DLL; l++) rsq += zs[l]*zs[l];
        rsq = fminf(rsq, 1.f - 1e-6f);
        float lam = 2.f/(1.f - rsq + 1e-6f);
        g_q[b*DKK + a] = red[0] * lam / sqrtf((float)DKK);
        if (a == 0) g_lam[b] = lam;
    }
}

// ======== K2: qB for all b — grid (8 r), 256 thr, smem-transposed basis ========
__global__ void __launch_bounds__(256) k_qB(
    const float* __restrict__ bb, const float* __restrict__ be,
    const float* __restrict__ bo) {
    extern __shared__ float Gs[];        // [128][129] padded
    __shared__ float qs[BB*DKK];
    int r = blockIdx.x, t = threadIdx.x;
    for (int idx = t; idx < BB*DKK; idx += 256) qs[idx] = g_q[idx];
    size_t rb = (size_t)r << 14;
    for (int idx = t; idx < DKK*DKK; idx += 256) {
        int i = idx >> 7, j = idx & 127;
        Gs[i*129 + j] = bb[rb + idx] + 0.5f*be[rb + idx] + 0.3f*bo[rb + idx];
    }
    __syncthreads();
    int j = t & 127;
    #pragma unroll
    for (int pass = 0; pass < 2; pass++) {
        int b = (t >> 7) + pass*2;
        float acc = 0.f;
        #pragma unroll 8
        for (int i = 0; i < DKK; i++)
            acc += qs[b*DKK + i] * (Gs[i*129 + j] - Gs[j*129 + i]);
        g_qB[(b*DCC + r)*DKK + j] = acc;
    }
}

// ======== K3: U[b,r,d] = sum_a e_r[a]*WK[a,d] — grid (8 dtiles, 4 b), 128 thr ========
__global__ void __launch_bounds__(128) k_u(const float* __restrict__ WK) {
    int b = blockIdx.y, t = threadIdx.x;
    int d = blockIdx.x*128 + t;
    __shared__ float e[9*DKK];
    for (int idx = t; idx < 9*DKK; idx += 128)
        e[idx] = (idx < DKK) ? g_q[b*DKK + idx] : g_qB[b*DCC*DKK + idx - DKK];
    __syncthreads();
    float acc[9];
    #pragma unroll
    for (int r = 0; r < 9; r++) acc[r] = 0.f;
    #pragma unroll 8
    for (int a = 0; a < DKK; a++) {
        float w = WK[(size_t)a*DD + d];
        #pragma unroll
        for (int r = 0; r < 9; r++) acc[r] += e[r*DKK + a]*w;
    }
    #pragma unroll
    for (int r = 0; r < 9; r++) g_u[b*9*DD + r*DD + d] = acc[r];
}

// ======== K4: scores + screening — grid (128 ntiles of 16, 4 b), 256 thr ========
// smem-staged u + software-pipelined x loads (depth 2).
__global__ void __launch_bounds__(256) k_score(
    const float* __restrict__ xk, const float* __restrict__ zq,
    const float* __restrict__ zk, const float* __restrict__ Wd,
    const float* __restrict__ logsig) {
    int b = blockIdx.y;
    int n0 = blockIdx.x * 16;
    int t = threadIdx.x, warp = t >> 5, lane = t & 31;
    __shared__ float su[9*DD];           // 36 KB
    __shared__ float scoef[16][DCC];
    __shared__ float sdist[16];
    __shared__ float szq[DLL];

    {   // stage u via float4
        const float4* src = (const float4*)(g_u + (size_t)b*9*DD);
        float4* dst = (float4*)su;
        #pragma unroll
        for (int i = 0; i < 9; i++) dst[t + i*256] = src[t + i*256];
    }
    if (t < DLL) szq[t] = zq[b*DLL + t];
    __syncthreads();

    // coeff + dist: warp handles rows 2w, 2w+1
    #pragma unroll
    for (int rr = 0; rr < 2; rr++) {
        int row = warp*2 + rr;
        int n = n0 + row;
        const float* zkp = zk + ((size_t)b*NN + n)*DLL;
        float d0 = szq[lane] - zkp[lane];
        float d1 = szq[lane+32] - zkp[lane+32];
        float dist = d0*d0 + d1*d1;
        #pragma unroll
        for (int o = 16; o; o >>= 1) dist += __shfl_xor_sync(0xffffffffu, dist, o);
        if (lane == 0) sdist[row] = dist;
        #pragma unroll
        for (int r = 0; r < DCC; r++) {
            float p = d0*Wd[r*DLL + lane] + d1*Wd[r*DLL + 32 + lane];
            #pragma unroll
            for (int o = 16; o; o >>= 1) p += __shfl_xor_sync(0xffffffffu, p, o);
            if (lane == 0) scoef[row][r] = p;
        }
    }
    __syncthreads();

    float lam = g_lam[b];
    float sfac = -expf(logsig[0]) * 0.5f * lam * lam;

    // 9-way dots, 2 rows/warp; pipeline x loads 1 iter ahead
    int row0 = warp*2;
    int n = n0 + row0;
    const float4* xp = (const float4*)(xk + ((size_t)b*NN + n)*DD);
    const float4* su4 = (const float4*)su;
    float acc[2][9];
    #pragma unroll
    for (int i = 0; i < 2; i++)
        #pragma unroll
        for (int r = 0; r < 9; r++) acc[i][r] = 0.f;

    float4 x0 = xp[lane];
    float4 x1 = xp[256 + lane];
    #pragma unroll
    for (int k = 0; k < 8; k++) {
        int dk = lane + 32*k;
        float4 nx0, nx1;
        if (k < 7) {
            nx0 = xp[dk + 32];
            nx1 = xp[256 + dk + 32];
        }
        #pragma unroll
        for (int g = 0; g < 3; g++) {
            float4 u0 = su4[(3*g+0)*256 + dk];
            float4 u1 = su4[(3*g+1)*256 + dk];
            float4 u2 = su4[(3*g+2)*256 + dk];
            acc[0][3*g+0] += x0.x*u0.x + x0.y*u0.y + x0.z*u0.z + x0.w*u0.w;
            acc[1][3*g+0] += x1.x*u0.x + x1.y*u0.y + x1.z*u0.z + x1.w*u0.w;
            acc[0][3*g+1] += x0.x*u1.x + x0.y*u1.y + x0.z*u1.z + x0.w*u1.w;
            acc[1][3*g+1] += x1.x*u1.x + x1.y*u1.y + x1.z*u1.z + x1.w*u1.w;
            acc[0][3*g+2] += x0.x*u2.x + x0.y*u2.y + x0.z*u2.z + x0.w*u2.w;
            acc[1][3*g+2] += x1.x*u2.x + x1.y*u2.y + x1.z*u2.z + x1.w*u2.w;
        }
        if (k < 7) { x0 = nx0; x1 = nx1; }
    }
    #pragma unroll
    for (int i = 0; i < 2; i++)
        #pragma unroll
        for (int r = 0; r < 9; r++) {
            #pragma unroll
            for (int o = 16; o; o >>= 1)
                acc[i][r] += __shfl_xor_sync(0xffffffffu, acc[i][r], o);
        }
    if (lane == 0) {
        #pragma unroll
        for (int i = 0; i < 2; i++) {
            float s = acc[i][0];
            #pragma unroll
            for (int r = 0; r < 8; r++) s += scoef[row0+i][r] * acc[i][r+1];
            g_score[b*NN + n + i] = s;
            g_screen[b*NN + n + i] = expf(sfac * sdist[row0+i]);
        }
    }
}

// ======== K5: softmax stats (in-block) + partial y — grid (4 dt, 16 nc, 4 b), 256 ====
__global__ void __launch_bounds__(256) k_y(const float* __restrict__ xk) {
    int b = blockIdx.z, nc = blockIdx.y;
    int t = threadIdx.x, dl = t & 63, strip = t >> 6;
    __shared__ float red[256];
    __shared__ float sw[128];
    __shared__ float4 red4[256];
    const float* sc = g_score + b*NN;

    // softmax stats over the full row (8KB, L2-hot)
    float m = -1e30f;
    #pragma unroll
    for (int i = t; i < NN; i += 256) m = fmaxf(m, sc[i]);
    red[t] = m; __syncthreads();
    for (int o = 128; o; o >>= 1) { if (t < o) red[t] = fmaxf(red[t], red[t+o]); __syncthreads(); }
    m = red[0]; __syncthreads();
    float z = 0.f;
    #pragma unroll
    for (int i = t; i < NN; i += 256) z += expf(sc[i] - m);
    red[t] = z; __syncthreads();
    for (int o = 128; o; o >>= 1) { if (t < o) red[t] += red[t+o]; __syncthreads(); }
    float Z = red[0]; __syncthreads();

    if (t < 128) {
        int n = nc*128 + t;
        sw[t] = expf(sc[n] - m) / Z * g_screen[b*NN + n];
    }
    __syncthreads();

    int d4 = blockIdx.x*64 + dl;
    const float4* xp = (const float4*)(xk + (size_t)(b*NN + nc*128)*DD);
    float4 acc = make_float4(0.f, 0.f, 0.f, 0.f);
    #pragma unroll 8
    for (int i = 0; i < 32; i++) {
        int nn = strip*32 + i;
        float w = sw[nn];
        float4 xv = xp[(size_t)nn*256 + d4];
        acc.x += w*xv.x; acc.y += w*xv.y; acc.z += w*xv.z; acc.w += w*xv.w;
    }
    red4[t] = acc; __syncthreads();
    if (strip == 0) {
        float4 a0 = red4[dl], a1 = red4[dl+64], a2 = red4[dl+128], a3 = red4[dl+192];
        float4 s = make_float4(a0.x+a1.x+a2.x+a3.x, a0.y+a1.y+a2.y+a3.y,
                               a0.z+a1.z+a2.z+a3.z, a0.w+a1.w+a2.w+a3.w);
        *(float4*)(g_yp + (size_t)(nc*BB + b)*DD + d4*4) = s;
    }
}

// ======== K6: ysum -> av = WV y -> out = WO av — grid (4 dtiles, 4 b), 256 thr ========
__global__ void __launch_bounds__(256) k_o(const float* __restrict__ WV,
                                           const float* __restrict__ WO,
                                           float* __restrict__ out) {
    int b = blockIdx.y;
    int t = threadIdx.x, warp = t >> 5, lane = t & 31;
    __shared__ float ysum[DD];
    __shared__ float sav[DKK];
    #pragma unroll
    for (int i = t; i < DD; i += 256) {
        float s = 0.f;
        #pragma unroll
        for (int p = 0; p < 16; p++) s += g_yp[(size_t)(p*BB + b)*DD + i];
        ysum[i] = s;
    }
    __syncthreads();
    // av[a] = ysum . WV[a,:]: warp computes 16 a's
    const float4* y4 = (const float4*)ysum;
    for (int ii = 0; ii < 16; ii++) {
        int a = warp*16 + ii;
        const float4* wv = (const float4*)(WV + (size_t)a*DD);
        float s = 0.f;
        #pragma unroll
        for (int k = 0; k < 8; k++) {
            float4 w = wv[lane + 32*k];
            float4 y = y4[lane + 32*k];
            s += y.x*w.x + y.y*w.y + y.z*w.z + y.w*w.w;
        }
        #pragma unroll
        for (int o = 16; o; o >>= 1) s += __shfl_xor_sync(0xffffffffu, s, o);
        if (lane == 0) sav[a] = s;
    }
    __syncthreads();
    int d = blockIdx.x*256 + t;
    float s = 0.f;
    const float4* wo = (const float4*)(WO + (size_t)d*DKK);
    #pragma unroll 8
    for (int a4 = 0; a4 < 32; a4++) {
        float4 wv = wo[a4];
        s += sav[a4*4+0]*wv.x + sav[a4*4+1]*wv.y + sav[a4*4+2]*wv.z + sav[a4*4+3]*wv.w;
    }
    out[b*DD + d] = s;
}

extern "C" void kernel_launch(void* const* d_in, const int* in_sizes, int n_in,
                              void* d_out, int out_size) {
    const float* x_query   = (const float*)d_in[0];
    const float* z_query   = (const float*)d_in[1];
    const float* x_keys    = (const float*)d_in[2];
    const float* z_keys    = (const float*)d_in[3];
    const float* W_Q       = (const float*)d_in[4];
    const float* W_Qz      = (const float*)d_in[5];
    const float* W_Qg      = (const float*)d_in[6];
    const float* W_K       = (const float*)d_in[7];
    const float* W_V       = (const float*)d_in[8];
    const float* W_O       = (const float*)d_in[9];
    const float* W_delta   = (const float*)d_in[10];
    const float* basis_b   = (const float*)d_in[11];
    const float* basis_e   = (const float*)d_in[12];
    const float* basis_o   = (const float*)d_in[13];
    const float* log_sigma = (const float*)d_in[14];
    float* out = (float*)d_out;

    static int smem_set = 0;
    if (!smem_set) {
        cudaFuncSetAttribute(k_qB, cudaFuncAttributeMaxDynamicSharedMemorySize,
                             DKK*129*sizeof(float));
        smem_set = 1;
    }

    k_q<<<dim3(DKK, BB), 128>>>(x_query, z_query, W_Q, W_Qz, W_Qg);
    k_qB<<<DCC, 256, DKK*129*sizeof(float)>>>(basis_b, basis_e, basis_o);
    k_u<<<dim3(8, BB), 128>>>(W_K);
    k_score<<<dim3(128, BB), 256>>>(x_keys, z_query, z_keys, W_delta, log_sigma);
    k_y<<<dim3(4, 16, BB), 256>>>(x_keys);
    k_o<<<dim3(4, BB), 256>>>(W_V, W_O, out);
}

// round 15
// speedup vs baseline: 1.1270x; 1.1270x over previous
#include <cuda_runtime.h>
#include <math.h>
#include <stdint.h>

// Shapes (fixed by the problem)
#define BB   4
#define NN   2048
#define DD   1024
#define DLL  64
#define DKK  128
#define DCC  8
#define NT   128            // n-tiles of 16 rows

// -------- device scratch (static: no allocations allowed) --------
__device__ float g_lam[BB];
__device__ float g_q[BB*DKK];        // q / tau
__device__ float g_qB[BB*DCC*DKK];   // (q/tau)^T basis_r
__device__ float g_u[BB*9*DD];       // u_0 = W_K^T (q/tau); u_r = W_K^T qB_r
__device__ float g_yp[NT*BB*DD];     // partial numerators N_b[d] per n-tile
__device__ float g_pm[NT*BB];        // per-tile max
__device__ float g_pz[NT*BB];        // per-tile sum-exp (no screen)

// ======== K1: q[b,a] (scaled by 1/tau) — grid (128 a, 4 b), 128 thr ========
__global__ void __launch_bounds__(128) k_q(
    const float* __restrict__ xq, const float* __restrict__ zq,
    const float* __restrict__ WQ, const float* __restrict__ WQz,
    const float* __restrict__ WQg) {
    int a = blockIdx.x, b = blockIdx.y;
    int t = threadIdx.x;
    __shared__ float zs[DLL];
    __shared__ float red[128];
    if (t < DLL) zs[t] = zq[b*DLL + t];
    __syncthreads();
    float s = 0.f;
    const float4* wq = (const float4*)(WQ + (size_t)a*DD);
    const float4* x  = (const float4*)(xq + (size_t)b*DD);
    #pragma unroll 2
    for (int d = t; d < DD/4; d += 128) {
        float4 wv = wq[d], xv = x[d];
        s += xv.x*wv.x + xv.y*wv.y + xv.z*wv.z + xv.w*wv.w;
    }
    if (t < DLL) s += zs[t]*WQz[a*DLL + t];
    const float* G = WQg + (size_t)a*DLL*DLL;
    #pragma unroll 4
    for (int idx = t; idx < DLL*DLL; idx += 128)
        s += G[idx]*zs[idx >> 6]*zs[idx & 63];
    red[t] = s; __syncthreads();
    for (int off = 64; off > 0; off >>= 1) {
        if (t < off) red[t] += red[t+off];
        __syncthreads();
    }
    if (t == 0) {
        float rsq = 0.f;
        for (int l = 0; l < DLL; l++) rsq += zs[l]*zs[l];
        rsq = fminf(rsq, 1.f - 1e-6f);
        float lam = 2.f/(1.f - rsq + 1e-6f);
        g_q[b*DKK + a] = red[0] * lam / sqrtf((float)DKK);
        if (a == 0) g_lam[b] = lam;
    }
}

// ======== K2: qB for all b — grid (8 r), 256 thr, smem-transposed basis ========
__global__ void __launch_bounds__(256) k_qB(
    const float* __restrict__ bb, const float* __restrict__ be,
    const float* __restrict__ bo) {
    extern __shared__ float Gs[];        // [128][129] padded
    __shared__ float qs[BB*DKK];
    int r = blockIdx.x, t = threadIdx.x;
    for (int idx = t; idx < BB*DKK; idx += 256) qs[idx] = g_q[idx];
    size_t rb = (size_t)r << 14;
    for (int idx = t; idx < DKK*DKK; idx += 256) {
        int i = idx >> 7, j = idx & 127;
        Gs[i*129 + j] = bb[rb + idx] + 0.5f*be[rb + idx] + 0.3f*bo[rb + idx];
    }
    __syncthreads();
    int j = t & 127;
    #pragma unroll
    for (int pass = 0; pass < 2; pass++) {
        int b = (t >> 7) + pass*2;
        float acc = 0.f;
        #pragma unroll 8
        for (int i = 0; i < DKK; i++)
            acc += qs[b*DKK + i] * (Gs[i*129 + j] - Gs[j*129 + i]);
        g_qB[(b*DCC + r)*DKK + j] = acc;
    }
}

// ======== K3: U[b,r,d] = sum_a e_r[a]*WK[a,d] — grid (8 dtiles, 4 b), 128 thr ========
__global__ void __launch_bounds__(128) k_u(const float* __restrict__ WK) {
    int b = blockIdx.y, t = threadIdx.x;
    int d = blockIdx.x*128 + t;
    __shared__ float e[9*DKK];
    for (int idx = t; idx < 9*DKK; idx += 128)
        e[idx] = (idx < DKK) ? g_q[b*DKK + idx] : g_qB[b*DCC*DKK + idx - DKK];
    __syncthreads();
    float acc[9];
    #pragma unroll
    for (int r = 0; r < 9; r++) acc[r] = 0.f;
    #pragma unroll 8
    for (int a = 0; a < DKK; a++) {
        float w = WK[(size_t)a*DD + d];
        #pragma unroll
        for (int r = 0; r < 9; r++) acc[r] += e[r*DKK + a]*w;
    }
    #pragma unroll
    for (int r = 0; r < 9; r++) g_u[b*9*DD + r*DD + d] = acc[r];
}

// ======== K4: fused scores + screening + partial softmax-y — grid (128, 4), 256 thr ====
__global__ void __launch_bounds__(256) k_sy(
    const float* __restrict__ xk, const float* __restrict__ zq,
    const float* __restrict__ zk, const float* __restrict__ Wd,
    const float* __restrict__ logsig) {
    int b = blockIdx.y;
    int n0 = blockIdx.x * 16;
    int t = threadIdx.x, warp = t >> 5, lane = t & 31;
    __shared__ float su[9*DD];           // 36 KB
    __shared__ float scoef[16][DCC];
    __shared__ float sdist[16];
    __shared__ float szq[DLL];
    __shared__ float sscore[16];
    __shared__ float sw[16];
    __shared__ float smz[2];

    {   // stage u via float4
        const float4* src = (const float4*)(g_u + (size_t)b*9*DD);
        float4* dst = (float4*)su;
        #pragma unroll
        for (int i = 0; i < 9; i++) dst[t + i*256] = src[t + i*256];
    }
    if (t < DLL) szq[t] = zq[b*DLL + t];
    __syncthreads();

    // coeff + dist: warp handles rows 2w, 2w+1
    #pragma unroll
    for (int rr = 0; rr < 2; rr++) {
        int row = warp*2 + rr;
        int n = n0 + row;
        const float* zkp = zk + ((size_t)b*NN + n)*DLL;
        float d0 = szq[lane] - zkp[lane];
        float d1 = szq[lane+32] - zkp[lane+32];
        float dist = d0*d0 + d1*d1;
        #pragma unroll
        for (int o = 16; o; o >>= 1) dist += __shfl_xor_sync(0xffffffffu, dist, o);
        if (lane == 0) sdist[row] = dist;
        #pragma unroll
        for (int r = 0; r < DCC; r++) {
            float p = d0*Wd[r*DLL + lane] + d1*Wd[r*DLL + 32 + lane];
            #pragma unroll
            for (int o = 16; o; o >>= 1) p += __shfl_xor_sync(0xffffffffu, p, o);
            if (lane == 0) scoef[row][r] = p;
        }
    }
    __syncthreads();

    float lam = g_lam[b];
    float sfac = -expf(logsig[0]) * 0.5f * lam * lam;

    // 9-way dots, 2 rows/warp (R7 measured-best form, no pipeline)
    int row0 = warp*2;
    int n = n0 + row0;
    const float4* xp = (const float4*)(xk + ((size_t)b*NN + n)*DD);
    const float4* su4 = (const float4*)su;
    float acc[2][9];
    #pragma unroll
    for (int i = 0; i < 2; i++)
        #pragma unroll
        for (int r = 0; r < 9; r++) acc[i][r] = 0.f;
    #pragma unroll
    for (int k = 0; k < 8; k++) {
        int dk = lane + 32*k;
        float4 x0 = xp[dk];
        float4 x1 = xp[256 + dk];
        #pragma unroll
        for (int g = 0; g < 3; g++) {
            float4 u0 = su4[(3*g+0)*256 + dk];
            float4 u1 = su4[(3*g+1)*256 + dk];
            float4 u2 = su4[(3*g+2)*256 + dk];
            acc[0][3*g+0] += x0.x*u0.x + x0.y*u0.y + x0.z*u0.z + x0.w*u0.w;
            acc[1][3*g+0] += x1.x*u0.x + x1.y*u0.y + x1.z*u0.z + x1.w*u0.w;
            acc[0][3*g+1] += x0.x*u1.x + x0.y*u1.y + x0.z*u1.z + x0.w*u1.w;
            acc[1][3*g+1] += x1.x*u1.x + x1.y*u1.y + x1.z*u1.z + x1.w*u1.w;
            acc[0][3*g+2] += x0.x*u2.x + x0.y*u2.y + x0.z*u2.z + x0.w*u2.w;
            acc[1][3*g+2] += x1.x*u2.x + x1.y*u2.y + x1.z*u2.z + x1.w*u2.w;
        }
    }
    #pragma unroll
    for (int i = 0; i < 2; i++)
        #pragma unroll
        for (int r = 0; r < 9; r++) {
            #pragma unroll
            for (int o = 16; o; o >>= 1)
                acc[i][r] += __shfl_xor_sync(0xffffffffu, acc[i][r], o);
        }
    if (lane == 0) {
        #pragma unroll
        for (int i = 0; i < 2; i++) {
            float s = acc[i][0];
            #pragma unroll
            for (int r = 0; r < 8; r++) s += scoef[row0+i][r] * acc[i][r+1];
            sscore[row0 + i] = s;
        }
    }
    __syncthreads();

    // block-local softmax partial (exact flash combine later)
    if (t == 0) {
        float m = -1e30f;
        #pragma unroll
        for (int i = 0; i < 16; i++) m = fmaxf(m, sscore[i]);
        float Z = 0.f;
        #pragma unroll
        for (int i = 0; i < 16; i++) {
            float e = expf(sscore[i] - m);
            Z += e;
            sw[i] = e * expf(sfac * sdist[i]);
        }
        smz[0] = 0.f;                    // unused slot (keeps layout simple)
        g_pm[blockIdx.x*BB + b] = m;
        g_pz[blockIdx.x*BB + b] = Z;
    }
    __syncthreads();

    // partial numerator: N[d] = sum_rows w[row]*x[row][d]; x rows are L1-hot
    const float4* xb = (const float4*)(xk + ((size_t)b*NN + n0)*DD);
    float4 ya = make_float4(0.f, 0.f, 0.f, 0.f);
    #pragma unroll
    for (int row = 0; row < 16; row++) {
        float wv = sw[row];
        float4 xv = xb[row*256 + t];
        ya.x += wv*xv.x; ya.y += wv*xv.y; ya.z += wv*xv.z; ya.w += wv*xv.w;
    }
    *(float4*)(g_yp + (size_t)(blockIdx.x*BB + b)*DD + t*4) = ya;
}

// ======== K5: combine partials -> y -> av = WV y -> out = WO av — grid (4 dt, 4 b) ====
__global__ void __launch_bounds__(256) k_o(const float* __restrict__ WV,
                                           const float* __restrict__ WO,
                                           float* __restrict__ out) {
    int b = blockIdx.y;
    int t = threadIdx.x, warp = t >> 5, lane = t & 31;
    __shared__ float ysum[DD];
    __shared__ float sav[DKK];
    __shared__ float sscale[NT];
    __shared__ float red[256];

    // global softmax stats from 128 tile partials
    float mv = (t < NT) ? g_pm[t*BB + b] : -1e30f;
    red[t] = mv; __syncthreads();
    for (int o = 128; o; o >>= 1) { if (t < o) red[t] = fmaxf(red[t], red[t+o]); __syncthreads(); }
    float M = red[0]; __syncthreads();
    float ez = 0.f;
    if (t < NT) {
        float e = expf(g_pm[t*BB + b] - M);
        sscale[t] = e;
        ez = e * g_pz[t*BB + b];
    }
    red[t] = ez; __syncthreads();
    for (int o = 128; o; o >>= 1) { if (t < o) red[t] += red[t+o]; __syncthreads(); }
    float Sinv = 1.f / red[0];
    __syncthreads();

    // ysum[d] = (sum_p scale_p * N_p[d]) / S
    #pragma unroll
    for (int i = t; i < DD; i += 256) {
        float s = 0.f;
        #pragma unroll 8
        for (int p = 0; p < NT; p++) s += sscale[p] * g_yp[(size_t)(p*BB + b)*DD + i];
        ysum[i] = s * Sinv;
    }
    __syncthreads();

    // av[a] = ysum . WV[a,:]: warp computes 16 a's
    const float4* y4 = (const float4*)ysum;
    for (int ii = 0; ii < 16; ii++) {
        int a = warp*16 + ii;
        const float4* wv = (const float4*)(WV + (size_t)a*DD);
        float s = 0.f;
        #pragma unroll
        for (int k = 0; k < 8; k++) {
            float4 w = wv[lane + 32*k];
            float4 y = y4[lane + 32*k];
            s += y.x*w.x + y.y*w.y + y.z*w.z + y.w*w.w;
        }
        #pragma unroll
        for (int o = 16; o; o >>= 1) s += __shfl_xor_sync(0xffffffffu, s, o);
        if (lane == 0) sav[a] = s;
    }
    __syncthreads();
    int d = blockIdx.x*256 + t;
    float s = 0.f;
    const float4* wo = (const float4*)(WO + (size_t)d*DKK);
    #pragma unroll 8
    for (int a4 = 0; a4 < 32; a4++) {
        float4 wv = wo[a4];
        s += sav[a4*4+0]*wv.x + sav[a4*4+1]*wv.y + sav[a4*4+2]*wv.z + sav[a4*4+3]*wv.w;
    }
    out[b*DD + d] = s;
}

extern "C" void kernel_launch(void* const* d_in, const int* in_sizes, int n_in,
                              void* d_out, int out_size) {
    const float* x_query   = (const float*)d_in[0];
    const float* z_query   = (const float*)d_in[1];
    const float* x_keys    = (const float*)d_in[2];
    const float* z_keys    = (const float*)d_in[3];
    const float* W_Q       = (const float*)d_in[4];
    const float* W_Qz      = (const float*)d_in[5];
    const float* W_Qg      = (const float*)d_in[6];
    const float* W_K       = (const float*)d_in[7];
    const float* W_V       = (const float*)d_in[8];
    const float* W_O       = (const float*)d_in[9];
    const float* W_delta   = (const float*)d_in[10];
    const float* basis_b   = (const float*)d_in[11];
    const float* basis_e   = (const float*)d_in[12];
    const float* basis_o   = (const float*)d_in[13];
    const float* log_sigma = (const float*)d_in[14];
    float* out = (float*)d_out;

    static int smem_set = 0;
    if (!smem_set) {
        cudaFuncSetAttribute(k_qB, cudaFuncAttributeMaxDynamicSharedMemorySize,
                             DKK*129*sizeof(float));
        smem_set = 1;
    }

    k_q<<<dim3(DKK, BB), 128>>>(x_query, z_query, W_Q, W_Qz, W_Qg);
    k_qB<<<DCC, 256, DKK*129*sizeof(float)>>>(basis_b, basis_e, basis_o);
    k_u<<<dim3(8, BB), 128>>>(W_K);
    k_sy<<<dim3(NT, BB), 256>>>(x_keys, z_query, z_keys, W_delta, log_sigma);
    k_o<<<dim3(4, BB), 256>>>(W_V, W_O, out);
}

// round 16
// speedup vs baseline: 1.5123x; 1.3419x over previous
#include <cuda_runtime.h>
#include <math.h>
#include <stdint.h>

// Shapes (fixed by the problem)
#define BB   4
#define NN   2048
#define DD   1024
#define DLL  64
#define DKK  128
#define DCC  8
#define NT   128            // n-tiles of 16 rows

// -------- device scratch (static: no allocations allowed) --------
__device__ float g_lam[BB];
__device__ float g_q[BB*DKK];        // q / tau
__device__ float g_qB[BB*DCC*DKK];   // (q/tau)^T basis_r
__device__ float g_u[BB*9*DD];       // u_0 = W_K^T (q/tau); u_r = W_K^T qB_r
__device__ float g_yp[NT*BB*DD];     // partial numerators N_b[d] per n-tile
__device__ float g_pm[NT*BB];        // per-tile max
__device__ float g_pz[NT*BB];        // per-tile sum-exp (no screen)
__device__ float g_y[BB*DD];         // combined, scaled y
__device__ float g_av[BB*DKK];       // av = W_V y

// ======== K1: q[b,a] (scaled by 1/tau) — grid (128 a, 4 b), 128 thr ========
__global__ void __launch_bounds__(128) k_q(
    const float* __restrict__ xq, const float* __restrict__ zq,
    const float* __restrict__ WQ, const float* __restrict__ WQz,
    const float* __restrict__ WQg) {
    int a = blockIdx.x, b = blockIdx.y;
    int t = threadIdx.x;
    __shared__ float zs[DLL];
    __shared__ float red[128];
    if (t < DLL) zs[t] = zq[b*DLL + t];
    __syncthreads();
    float s = 0.f;
    const float4* wq = (const float4*)(WQ + (size_t)a*DD);
    const float4* x  = (const float4*)(xq + (size_t)b*DD);
    #pragma unroll 2
    for (int d = t; d < DD/4; d += 128) {
        float4 wv = wq[d], xv = x[d];
        s += xv.x*wv.x + xv.y*wv.y + xv.z*wv.z + xv.w*wv.w;
    }
    if (t < DLL) s += zs[t]*WQz[a*DLL + t];
    const float* G = WQg + (size_t)a*DLL*DLL;
    #pragma unroll 4
    for (int idx = t; idx < DLL*DLL; idx += 128)
        s += G[idx]*zs[idx >> 6]*zs[idx & 63];
    red[t] = s; __syncthreads();
    for (int off = 64; off > 0; off >>= 1) {
        if (t < off) red[t] += red[t+off];
        __syncthreads();
    }
    if (t == 0) {
        float rsq = 0.f;
        for (int l = 0; l < DLL; l++) rsq += zs[l]*zs[l];
        rsq = fminf(rsq, 1.f - 1e-6f);
        float lam = 2.f/(1.f - rsq + 1e-6f);
        g_q[b*DKK + a] = red[0] * lam / sqrtf((float)DKK);
        if (a == 0) g_lam[b] = lam;
    }
}

// ======== K2: qB for all b — grid (8 r), 256 thr, smem-transposed basis ========
__global__ void __launch_bounds__(256) k_qB(
    const float* __restrict__ bb, const float* __restrict__ be,
    const float* __restrict__ bo) {
    extern __shared__ float Gs[];        // [128][129] padded
    __shared__ float qs[BB*DKK];
    int r = blockIdx.x, t = threadIdx.x;
    for (int idx = t; idx < BB*DKK; idx += 256) qs[idx] = g_q[idx];
    size_t rb = (size_t)r << 14;
    for (int idx = t; idx < DKK*DKK; idx += 256) {
        int i = idx >> 7, j = idx & 127;
        Gs[i*129 + j] = bb[rb + idx] + 0.5f*be[rb + idx] + 0.3f*bo[rb + idx];
    }
    __syncthreads();
    int j = t & 127;
    #pragma unroll
    for (int pass = 0; pass < 2; pass++) {
        int b = (t >> 7) + pass*2;
        float acc = 0.f;
        #pragma unroll 8
        for (int i = 0; i < DKK; i++)
            acc += qs[b*DKK + i] * (Gs[i*129 + j] - Gs[j*129 + i]);
        g_qB[(b*DCC + r)*DKK + j] = acc;
    }
}

// ======== K3: U[b,r,d] = sum_a e_r[a]*WK[a,d] — grid (8 dtiles, 4 b), 128 thr ========
__global__ void __launch_bounds__(128) k_u(const float* __restrict__ WK) {
    int b = blockIdx.y, t = threadIdx.x;
    int d = blockIdx.x*128 + t;
    __shared__ float e[9*DKK];
    for (int idx = t; idx < 9*DKK; idx += 128)
        e[idx] = (idx < DKK) ? g_q[b*DKK + idx] : g_qB[b*DCC*DKK + idx - DKK];
    __syncthreads();
    float acc[9];
    #pragma unroll
    for (int r = 0; r < 9; r++) acc[r] = 0.f;
    #pragma unroll 8
    for (int a = 0; a < DKK; a++) {
        float w = WK[(size_t)a*DD + d];
        #pragma unroll
        for (int r = 0; r < 9; r++) acc[r] += e[r*DKK + a]*w;
    }
    #pragma unroll
    for (int r = 0; r < 9; r++) g_u[b*9*DD + r*DD + d] = acc[r];
}

// ======== K4: fused scores + screening + partial softmax-y — grid (128, 4), 256 thr ====
__global__ void __launch_bounds__(256) k_sy(
    const float* __restrict__ xk, const float* __restrict__ zq,
    const float* __restrict__ zk, const float* __restrict__ Wd,
    const float* __restrict__ logsig) {
    int b = blockIdx.y;
    int n0 = blockIdx.x * 16;
    int t = threadIdx.x, warp = t >> 5, lane = t & 31;
    __shared__ float su[9*DD];           // 36 KB
    __shared__ float scoef[16][DCC];
    __shared__ float sdist[16];
    __shared__ float szq[DLL];
    __shared__ float sscore[16];
    __shared__ float sw[16];

    {   // stage u via float4
        const float4* src = (const float4*)(g_u + (size_t)b*9*DD);
        float4* dst = (float4*)su;
        #pragma unroll
        for (int i = 0; i < 9; i++) dst[t + i*256] = src[t + i*256];
    }
    if (t < DLL) szq[t] = zq[b*DLL + t];
    __syncthreads();

    // coeff + dist: warp handles rows 2w, 2w+1
    #pragma unroll
    for (int rr = 0; rr < 2; rr++) {
        int row = warp*2 + rr;
        int n = n0 + row;
        const float* zkp = zk + ((size_t)b*NN + n)*DLL;
        float d0 = szq[lane] - zkp[lane];
        float d1 = szq[lane+32] - zkp[lane+32];
        float dist = d0*d0 + d1*d1;
        #pragma unroll
        for (int o = 16; o; o >>= 1) dist += __shfl_xor_sync(0xffffffffu, dist, o);
        if (lane == 0) sdist[row] = dist;
        #pragma unroll
        for (int r = 0; r < DCC; r++) {
            float p = d0*Wd[r*DLL + lane] + d1*Wd[r*DLL + 32 + lane];
            #pragma unroll
            for (int o = 16; o; o >>= 1) p += __shfl_xor_sync(0xffffffffu, p, o);
            if (lane == 0) scoef[row][r] = p;
        }
    }
    __syncthreads();

    float lam = g_lam[b];
    float sfac = -expf(logsig[0]) * 0.5f * lam * lam;

    // 9-way dots, 2 rows/warp
    int row0 = warp*2;
    int n = n0 + row0;
    const float4* xp = (const float4*)(xk + ((size_t)b*NN + n)*DD);
    const float4* su4 = (const float4*)su;
    float acc[2][9];
    #pragma unroll
    for (int i = 0; i < 2; i++)
        #pragma unroll
        for (int r = 0; r < 9; r++) acc[i][r] = 0.f;
    #pragma unroll
    for (int k = 0; k < 8; k++) {
        int dk = lane + 32*k;
        float4 x0 = xp[dk];
        float4 x1 = xp[256 + dk];
        #pragma unroll
        for (int g = 0; g < 3; g++) {
            float4 u0 = su4[(3*g+0)*256 + dk];
            float4 u1 = su4[(3*g+1)*256 + dk];
            float4 u2 = su4[(3*g+2)*256 + dk];
            acc[0][3*g+0] += x0.x*u0.x + x0.y*u0.y + x0.z*u0.z + x0.w*u0.w;
            acc[1][3*g+0] += x1.x*u0.x + x1.y*u0.y + x1.z*u0.z + x1.w*u0.w;
            acc[0][3*g+1] += x0.x*u1.x + x0.y*u1.y + x0.z*u1.z + x0.w*u1.w;
            acc[1][3*g+1] += x1.x*u1.x + x1.y*u1.y + x1.z*u1.z + x1.w*u1.w;
            acc[0][3*g+2] += x0.x*u2.x + x0.y*u2.y + x0.z*u2.z + x0.w*u2.w;
            acc[1][3*g+2] += x1.x*u2.x + x1.y*u2.y + x1.z*u2.z + x1.w*u2.w;
        }
    }
    #pragma unroll
    for (int i = 0; i < 2; i++)
        #pragma unroll
        for (int r = 0; r < 9; r++) {
            #pragma unroll
            for (int o = 16; o; o >>= 1)
                acc[i][r] += __shfl_xor_sync(0xffffffffu, acc[i][r], o);
        }
    if (lane == 0) {
        #pragma unroll
        for (int i = 0; i < 2; i++) {
            float s = acc[i][0];
            #pragma unroll
            for (int r = 0; r < 8; r++) s += scoef[row0+i][r] * acc[i][r+1];
            sscore[row0 + i] = s;
        }
    }
    __syncthreads();

    // block-local softmax partial (exact flash combine later)
    if (t == 0) {
        float m = -1e30f;
        #pragma unroll
        for (int i = 0; i < 16; i++) m = fmaxf(m, sscore[i]);
        float Z = 0.f;
        #pragma unroll
        for (int i = 0; i < 16; i++) {
            float e = expf(sscore[i] - m);
            Z += e;
            sw[i] = e * expf(sfac * sdist[i]);
        }
        g_pm[blockIdx.x*BB + b] = m;
        g_pz[blockIdx.x*BB + b] = Z;
    }
    __syncthreads();

    // partial numerator: N[d] = sum_rows w[row]*x[row][d]; x rows are L1-hot
    const float4* xb = (const float4*)(xk + ((size_t)b*NN + n0)*DD);
    float4 ya = make_float4(0.f, 0.f, 0.f, 0.f);
    #pragma unroll
    for (int row = 0; row < 16; row++) {
        float wv = sw[row];
        float4 xv = xb[row*256 + t];
        ya.x += wv*xv.x; ya.y += wv*xv.y; ya.z += wv*xv.z; ya.w += wv*xv.w;
    }
    *(float4*)(g_yp + (size_t)(blockIdx.x*BB + b)*DD + t*4) = ya;
}

// ======== K5: combine partials -> scaled y — grid (32 dtiles, 4 b), 128 thr ========
__global__ void __launch_bounds__(128) k_yr() {
    int b = blockIdx.y;
    int t = threadIdx.x, dl = t & 31, strip = t >> 5;   // 4 strips of 32 partials
    __shared__ float sscale[NT];
    __shared__ float red[128];

    // global softmax stats from the 128 tile partials (tiny, redundant per block)
    float mv = (t < NT) ? g_pm[t*BB + b] : -1e30f;
    red[t] = mv; __syncthreads();
    for (int o = 64; o; o >>= 1) { if (t < o) red[t] = fmaxf(red[t], red[t+o]); __syncthreads(); }
    float M = red[0]; __syncthreads();
    float ez = 0.f;
    if (t < NT) {
        float e = expf(g_pm[t*BB + b] - M);
        sscale[t] = e;
        ez = e * g_pz[t*BB + b];
    }
    red[t] = ez; __syncthreads();
    for (int o = 64; o; o >>= 1) { if (t < o) red[t] += red[t+o]; __syncthreads(); }
    float Sinv = 1.f / red[0];
    __syncthreads();

    // y[d] = Sinv * sum_p scale_p * N_p[d], d-tile of 32
    int d = blockIdx.x*32 + dl;
    float acc = 0.f;
    #pragma unroll 8
    for (int pp = 0; pp < 32; pp++) {
        int p = strip*32 + pp;
        acc += sscale[p] * g_yp[(size_t)(p*BB + b)*DD + d];
    }
    red[t] = acc; __syncthreads();
    if (strip == 0)
        g_y[b*DD + d] = (red[dl] + red[dl+32] + red[dl+64] + red[dl+96]) * Sinv;
}

// ======== K6: av[b,a] = y . WV[a,:] — grid (128 a, 4 b), 128 thr ========
__global__ void __launch_bounds__(128) k_av(const float* __restrict__ WV) {
    int a = blockIdx.x, b = blockIdx.y;
    int t = threadIdx.x;
    __shared__ float red[128];
    const float4* wv = (const float4*)(WV + (size_t)a*DD);
    const float4* y4 = (const float4*)(g_y + (size_t)b*DD);
    float s = 0.f;
    #pragma unroll
    for (int i = 0; i < 2; i++) {
        float4 w = wv[t + i*128];
        float4 y = y4[t + i*128];
        s += y.x*w.x + y.y*w.y + y.z*w.z + y.w*w.w;
    }
    red[t] = s; __syncthreads();
    for (int o = 64; o; o >>= 1) { if (t < o) red[t] += red[t+o]; __syncthreads(); }
    if (t == 0) g_av[b*DKK + a] = red[0];
}

// ======== K7: out[b,d] = av . WO[d,:] — grid (4 dtiles, 4 b), 256 thr ========
__global__ void __launch_bounds__(256) k_out(const float* __restrict__ WO,
                                             float* __restrict__ out) {
    int b = blockIdx.y;
    int t = threadIdx.x;
    int d = blockIdx.x*256 + t;
    __shared__ float av[DKK];
    if (t < DKK) av[t] = g_av[b*DKK + t];
    __syncthreads();
    float s = 0.f;
    const float4* wo = (const float4*)(WO + (size_t)d*DKK);
    #pragma unroll 8
    for (int a4 = 0; a4 < 32; a4++) {
        float4 wv = wo[a4];
        s += av[a4*4+0]*wv.x + av[a4*4+1]*wv.y + av[a4*4+2]*wv.z + av[a4*4+3]*wv.w;
    }
    out[b*DD + d] = s;
}

extern "C" void kernel_launch(void* const* d_in, const int* in_sizes, int n_in,
                              void* d_out, int out_size) {
    const float* x_query   = (const float*)d_in[0];
    const float* z_query   = (const float*)d_in[1];
    const float* x_keys    = (const float*)d_in[2];
    const float* z_keys    = (const float*)d_in[3];
    const float* W_Q       = (const float*)d_in[4];
    const float* W_Qz      = (const float*)d_in[5];
    const float* W_Qg      = (const float*)d_in[6];
    const float* W_K       = (const float*)d_in[7];
    const float* W_V       = (const float*)d_in[8];
    const float* W_O       = (const float*)d_in[9];
    const float* W_delta   = (const float*)d_in[10];
    const float* basis_b   = (const float*)d_in[11];
    const float* basis_e   = (const float*)d_in[12];
    const float* basis_o   = (const float*)d_in[13];
    const float* log_sigma = (const float*)d_in[14];
    float* out = (float*)d_out;

    static int smem_set = 0;
    if (!smem_set) {
        cudaFuncSetAttribute(k_qB, cudaFuncAttributeMaxDynamicSharedMemorySize,
                             DKK*129*sizeof(float));
        smem_set = 1;
    }

    k_q<<<dim3(DKK, BB), 128>>>(x_query, z_query, W_Q, W_Qz, W_Qg);
    k_qB<<<DCC, 256, DKK*129*sizeof(float)>>>(basis_b, basis_e, basis_o);
    k_u<<<dim3(8, BB), 128>>>(W_K);
    k_sy<<<dim3(NT, BB), 256>>>(x_keys, z_query, z_keys, W_delta, log_sigma);
    k_yr<<<dim3(32, BB), 128>>>();
    k_av<<<dim3(DKK, BB), 128>>>(W_V);
    k_out<<<dim3(4, BB), 256>>>(W_O, out);
}